// round 10
// baseline (speedup 1.0000x reference)
#include <cuda_runtime.h>
#include <cstdint>

#define NN 50000
#define NE 1600000

// Scratch (static device globals — no allocation in kernel_launch)
__device__ float g_P[NN * 64];     // P[n][j] = fR_b1[j] + sum_k x[n][k] * fR_W1[k][j]      (dst part)
__device__ float g_Q[NN * 64];     // Q[n][j] =            sum_k x[n][k] * fR_W1[16+k][j]   (src part)
__device__ float g_agg[NN * 16];   // scatter-sum of e_new by dst

// ---------------------------------------------------------------------------
// K0: zero the aggregation buffer
// ---------------------------------------------------------------------------
__global__ void zero_agg_kernel() {
    int i = blockIdx.x * 256 + threadIdx.x;
    if (i < NN * 16 / 4) ((float4*)g_agg)[i] = make_float4(0.f, 0.f, 0.f, 0.f);
}

// ---------------------------------------------------------------------------
// K1: per-node precompute  P = x@W1[0:16] + b1,  Q = x@W1[16:32]
// ---------------------------------------------------------------------------
__global__ void __launch_bounds__(256) precompute_pq(
    const float* __restrict__ x, const float* __restrict__ W1,
    const float* __restrict__ b1)
{
    int idx = blockIdx.x * 256 + threadIdx.x;       // exactly NN*64 threads
    int n = idx >> 6, j = idx & 63;
    float p = b1[j], q = 0.f;
#pragma unroll
    for (int k = 0; k < 16; k++) {
        float xv = __ldg(x + n * 16 + k);           // broadcast within warp
        p = fmaf(xv, W1[k * 64 + j], p);
        q = fmaf(xv, W1[(16 + k) * 64 + j], q);
    }
    g_P[idx] = p;
    g_Q[idx] = q;
}

// ---------------------------------------------------------------------------
// K2: edge kernel. 128 edges/block, 128 threads = 32 rows (4 edges each)
//     x 4 hidden col-groups (16 j each). Scalar fp32, L1/MIO-minimized:
//   s_ET[k][edge] pad-132 — one LDS.128 per k gives this thread's 4 e-values
//   s_W1x / s_W2x interleaved [.][.][tx][4] — conflict-free LDS.128
//   GEMM2 edge-at-a-time; cross-tx reduce via halving tree (12 SHFL/edge).
// ---------------------------------------------------------------------------
__global__ void __launch_bounds__(128) edge_kernel(
    const int* __restrict__ ei, const float* __restrict__ e_in,
    const float* __restrict__ W1, const float* __restrict__ W2,
    const float* __restrict__ b2, float* __restrict__ e_out,
    int block_off)
{
    __shared__ __align__(16) float s_ET[16][132];   // e transposed, pad 132
    __shared__ __align__(16) float s_W1x[1024];     // [k][q][tx][i] = W1c[k][tx*16+q*4+i]
    __shared__ __align__(16) float s_W2x[1024];     // [jj][cq][tx][i] = W2[tx*16+jj][cq*4+i]

    const int tid = threadIdx.x;
    const int tx = tid & 3;          // hidden col-group (16 j each)
    const int ty = tid >> 2;         // edge-quad row (4 edges each)
    const int base = (blockIdx.x + block_off) * 128;
    const int eb = ty * 4;

    // ---- bias quad this lane will own (c = tx*4..+3) ----
    const float4 bb = ((const float4*)b2)[tx];

    // ---- indices for this thread's 4 edges (front-loaded; tx-dup dedups) ----
    int sidx[4], didx[4];
#pragma unroll
    for (int p = 0; p < 4; p++) {
        sidx[p] = ei[base + eb + p];
        didx[p] = ei[NE + base + eb + p];
    }

    // ---- gather-add P[dst]+Q[src] into acc (overlaps with staging below) ----
    float acc[4][16];
#pragma unroll
    for (int p = 0; p < 4; p++) {
#pragma unroll
        for (int q = 0; q < 4; q++) {
            float4 pv = *((const float4*)(g_P + didx[p] * 64 + tx * 16) + q);
            float4 qv = *((const float4*)(g_Q + sidx[p] * 64 + tx * 16) + q);
            acc[p][q * 4 + 0] = pv.x + qv.x;
            acc[p][q * 4 + 1] = pv.y + qv.y;
            acc[p][q * 4 + 2] = pv.z + qv.z;
            acc[p][q * 4 + 3] = pv.w + qv.w;
        }
    }

    // ---- stage e tile transposed: 128 edges x 16 = 512 float4 loads ----
#pragma unroll
    for (int r = 0; r < 4; r++) {
        int idx = r * 128 + tid;                     // 0..511
        float4 v = ((const float4*)e_in)[base * 4 + idx];
        int edge = idx >> 2, part = idx & 3;
        s_ET[part * 4 + 0][edge] = v.x;
        s_ET[part * 4 + 1][edge] = v.y;
        s_ET[part * 4 + 2][edge] = v.z;
        s_ET[part * 4 + 3][edge] = v.w;
    }
    // ---- stage W1c interleaved ----
#pragma unroll
    for (int r = 0; r < 8; r++) {
        int t = r * 128 + tid;                       // 0..1023
        int k = t >> 6, rem = t & 63;
        int q = rem >> 4, txx = (rem >> 2) & 3, i = rem & 3;
        s_W1x[t] = W1[(32 + k) * 64 + txx * 16 + q * 4 + i];
    }
    // ---- stage W2 interleaved ----
#pragma unroll
    for (int r = 0; r < 8; r++) {
        int t = r * 128 + tid;                       // 0..1023
        int jj = t >> 6, rem = t & 63;
        int cq = rem >> 4, txx = (rem >> 2) & 3, i = rem & 3;
        s_W2x[t] = W2[(txx * 16 + jj) * 16 + cq * 4 + i];
    }
    __syncthreads();

    // ---- GEMM1: acc += e @ W1c.  Per k: 1 LDS.128 e (4 edges) + 4 LDS.128 w ----
#pragma unroll
    for (int k = 0; k < 16; k++) {
        float4 ev = *(const float4*)&s_ET[k][eb];
        const float av[4] = {ev.x, ev.y, ev.z, ev.w};
#pragma unroll
        for (int q = 0; q < 4; q++) {
            float4 w = *(const float4*)&s_W1x[k * 64 + q * 16 + tx * 4];
#pragma unroll
            for (int p = 0; p < 4; p++) {
                acc[p][q * 4 + 0] = fmaf(av[p], w.x, acc[p][q * 4 + 0]);
                acc[p][q * 4 + 1] = fmaf(av[p], w.y, acc[p][q * 4 + 1]);
                acc[p][q * 4 + 2] = fmaf(av[p], w.z, acc[p][q * 4 + 2]);
                acc[p][q * 4 + 3] = fmaf(av[p], w.w, acc[p][q * 4 + 3]);
            }
        }
    }

    // ---- ReLU ----
#pragma unroll
    for (int p = 0; p < 4; p++)
#pragma unroll
        for (int jj = 0; jj < 16; jj++)
            acc[p][jj] = fmaxf(acc[p][jj], 0.f);

    // ---- GEMM2 + reduce + epilogue, one edge at a time ----
    const bool hi2 = (tx & 2) != 0;
    const bool hi1 = (tx & 1) != 0;
#pragma unroll
    for (int p = 0; p < 4; p++) {
        // partials for all 16 c over this thread's 16 j
        float o[16];
#pragma unroll
        for (int c = 0; c < 16; c++) o[c] = 0.f;
#pragma unroll
        for (int jj = 0; jj < 16; jj++) {
            float hh = acc[p][jj];
#pragma unroll
            for (int cq = 0; cq < 4; cq++) {
                float4 w = *(const float4*)&s_W2x[jj * 64 + cq * 16 + tx * 4];
                o[cq * 4 + 0] = fmaf(hh, w.x, o[cq * 4 + 0]);
                o[cq * 4 + 1] = fmaf(hh, w.y, o[cq * 4 + 1]);
                o[cq * 4 + 2] = fmaf(hh, w.z, o[cq * 4 + 2]);
                o[cq * 4 + 3] = fmaf(hh, w.w, o[cq * 4 + 3]);
            }
        }
        // stage 1 (xor 2): send the 8 c-values the partner keeps; keep my half
        float keep[8];
#pragma unroll
        for (int i = 0; i < 8; i++) {
            float send = hi2 ? o[i] : o[8 + i];
            float recv = __shfl_xor_sync(0xffffffffu, send, 2);
            keep[i] = (hi2 ? o[8 + i] : o[i]) + recv;
        }
        // stage 2 (xor 1): final lane tx owns c = tx*4..+3
        float fin[4];
#pragma unroll
        for (int i = 0; i < 4; i++) {
            float send = hi1 ? keep[i] : keep[4 + i];
            float recv = __shfl_xor_sync(0xffffffffu, send, 1);
            fin[i] = (hi1 ? keep[4 + i] : keep[i]) + recv;
        }
        // epilogue: +b2, one float4 store, 4 scalar atomics
        float4 ov = make_float4(fin[0] + bb.x, fin[1] + bb.y,
                                fin[2] + bb.z, fin[3] + bb.w);
        int edge = base + eb + p;
        *(float4*)&e_out[edge * 16 + tx * 4] = ov;
        float* ap = g_agg + didx[p] * 16 + tx * 4;
        atomicAdd(ap + 0, ov.x);
        atomicAdd(ap + 1, ov.y);
        atomicAdd(ap + 2, ov.z);
        atomicAdd(ap + 3, ov.w);
    }
}

// ---------------------------------------------------------------------------
// K3: node MLP  x_new = fO(concat(x, agg)). One node per thread; weights in smem.
// ---------------------------------------------------------------------------
__global__ void __launch_bounds__(128) node_kernel(
    const float* __restrict__ x,
    const float* __restrict__ W1, const float* __restrict__ b1,
    const float* __restrict__ W2, const float* __restrict__ b2,
    float* __restrict__ x_out)
{
    __shared__ float sW1[32 * 64];
    __shared__ float sW2[64 * 16];
    __shared__ float sb1[64];
    __shared__ float sb2[16];
    int tid = threadIdx.x;
#pragma unroll
    for (int r = 0; r < 16; r++) sW1[r * 128 + tid] = W1[r * 128 + tid];
#pragma unroll
    for (int r = 0; r < 8; r++) sW2[r * 128 + tid] = W2[r * 128 + tid];
    if (tid < 64) sb1[tid] = b1[tid];
    if (tid < 16) sb2[tid] = b2[tid];
    __syncthreads();

    int n = blockIdx.x * 128 + tid;
    if (n >= NN) return;

    float in[32];
#pragma unroll
    for (int q = 0; q < 4; q++) {
        float4 v = ((const float4*)x)[n * 4 + q];
        in[q * 4 + 0] = v.x; in[q * 4 + 1] = v.y;
        in[q * 4 + 2] = v.z; in[q * 4 + 3] = v.w;
        float4 a = ((const float4*)g_agg)[n * 4 + q];
        in[16 + q * 4 + 0] = a.x; in[16 + q * 4 + 1] = a.y;
        in[16 + q * 4 + 2] = a.z; in[16 + q * 4 + 3] = a.w;
    }
    float o[16];
#pragma unroll
    for (int c = 0; c < 16; c++) o[c] = sb2[c];
    for (int j = 0; j < 64; j++) {                   // keep j-loop rolled (I-cache)
        float h = sb1[j];
#pragma unroll
        for (int k = 0; k < 32; k++) h = fmaf(in[k], sW1[k * 64 + j], h);
        h = fmaxf(h, 0.f);
#pragma unroll
        for (int c = 0; c < 16; c++) o[c] = fmaf(h, sW2[j * 16 + c], o[c]);
    }
#pragma unroll
    for (int q = 0; q < 4; q++)
        ((float4*)x_out)[n * 4 + q] =
            make_float4(o[q * 4 + 0], o[q * 4 + 1], o[q * 4 + 2], o[q * 4 + 3]);
}

// ---------------------------------------------------------------------------
extern "C" void kernel_launch(void* const* d_in, const int* in_sizes, int n_in,
                              void* d_out, int out_size)
{
    const float* x     = (const float*)d_in[0];
    const int*   ei    = (const int*)d_in[1];    // edge_index: int32 (JAX x64 disabled)
    const float* e     = (const float*)d_in[2];
    const float* fRW1  = (const float*)d_in[3];
    const float* fRb1  = (const float*)d_in[4];
    const float* fRW2  = (const float*)d_in[5];
    const float* fRb2  = (const float*)d_in[6];
    const float* fOW1  = (const float*)d_in[7];
    const float* fOb1  = (const float*)d_in[8];
    const float* fOW2  = (const float*)d_in[9];
    const float* fOb2  = (const float*)d_in[10];

    float* x_new = (float*)d_out;            // [NN, 16]
    float* e_new = x_new + NN * 16;          // [NE, 16]

    const int EB = NE / 128;                 // 12500 edge blocks total
    const int Q  = EB / 4;                   // 4 quarter launches (profiling slots)

    precompute_pq<<<(NN * 64) / 256, 256>>>(x, fRW1, fRb1);
    zero_agg_kernel<<<(NN * 16 / 4 + 255) / 256, 256>>>();
    edge_kernel<<<Q, 128>>>(ei, e, fRW1, fRW2, fRb2, e_new, 0 * Q);
    edge_kernel<<<Q, 128>>>(ei, e, fRW1, fRW2, fRb2, e_new, 1 * Q);
    edge_kernel<<<Q, 128>>>(ei, e, fRW1, fRW2, fRb2, e_new, 2 * Q);
    edge_kernel<<<Q, 128>>>(ei, e, fRW1, fRW2, fRb2, e_new, 3 * Q);
    node_kernel<<<(NN + 127) / 128, 128>>>(x, fOW1, fOb1, fOW2, fOb2, x_new);
}

// round 11
// speedup vs baseline: 1.3539x; 1.3539x over previous
#include <cuda_runtime.h>
#include <cstdint>

#define NN 50000
#define NE 1600000

// Scratch (static device globals — no allocation in kernel_launch)
__device__ float g_P[NN * 64];     // P[n][j] = fR_b1[j] + sum_k x[n][k] * fR_W1[k][j]      (dst part)
__device__ float g_Q[NN * 64];     // Q[n][j] =            sum_k x[n][k] * fR_W1[16+k][j]   (src part)
__device__ float g_agg[NN * 16];   // scatter-sum of e_new by dst

// ---------------------------------------------------------------------------
// K0: zero the aggregation buffer
// ---------------------------------------------------------------------------
__global__ void zero_agg_kernel() {
    int i = blockIdx.x * 256 + threadIdx.x;
    if (i < NN * 16 / 4) ((float4*)g_agg)[i] = make_float4(0.f, 0.f, 0.f, 0.f);
}

// ---------------------------------------------------------------------------
// K1: per-node precompute  P = x@W1[0:16] + b1,  Q = x@W1[16:32]
// ---------------------------------------------------------------------------
__global__ void __launch_bounds__(256) precompute_pq(
    const float* __restrict__ x, const float* __restrict__ W1,
    const float* __restrict__ b1)
{
    int idx = blockIdx.x * 256 + threadIdx.x;       // exactly NN*64 threads
    int n = idx >> 6, j = idx & 63;
    float p = b1[j], q = 0.f;
#pragma unroll
    for (int k = 0; k < 16; k++) {
        float xv = __ldg(x + n * 16 + k);           // broadcast within warp
        p = fmaf(xv, W1[k * 64 + j], p);
        q = fmaf(xv, W1[(16 + k) * 64 + j], q);
    }
    g_P[idx] = p;
    g_Q[idx] = q;
}

// ---------------------------------------------------------------------------
// K2: edge kernel (R9 structure, regs capped at 128 via launch_bounds min-4-
//     blocks). 128 edges/block, 128 threads = 32 rows (4 edges each) x 4
//     hidden col-groups (16 j each). Scalar fp32, L1-work-minimized:
//   s_ET[k][edge] pad-132 — one LDS.128 per k gives this thread's 4 e-values
//   s_W1x / s_W2x interleaved [.][.][tx][4] — conflict-free LDS.128 broadcast
//   GEMM2 computed in two 8-column halves to cap live registers.
// ---------------------------------------------------------------------------
__global__ void __launch_bounds__(128, 4) edge_kernel(
    const int* __restrict__ ei, const float* __restrict__ e_in,
    const float* __restrict__ W1, const float* __restrict__ W2,
    const float* __restrict__ b2, float* __restrict__ e_out,
    int block_off)
{
    __shared__ __align__(16) float s_ET[16][132];   // e transposed, pad 132
    __shared__ __align__(16) float s_W1x[1024];     // [k][q][tx][i] = W1c[k][tx*16+q*4+i]
    __shared__ __align__(16) float s_W2x[1024];     // [jj][cq][tx][i] = W2[tx*16+jj][cq*4+i]
    __shared__ float s_b2[16];

    const int tid = threadIdx.x;
    const int tx = tid & 3;          // hidden col-group (16 j each)
    const int ty = tid >> 2;         // edge-quad row (4 edges each)
    const int base = (blockIdx.x + block_off) * 128;
    const int eb = ty * 4;

    // ---- indices for this thread's 4 edges (front-loaded; tx-dup dedups) ----
    int sidx[4], didx[4];
#pragma unroll
    for (int p = 0; p < 4; p++) {
        sidx[p] = ei[base + eb + p];
        didx[p] = ei[NE + base + eb + p];
    }

    // ---- gather-add P[dst]+Q[src] into acc (overlaps with staging below) ----
    float acc[4][16];
#pragma unroll
    for (int p = 0; p < 4; p++) {
#pragma unroll
        for (int q = 0; q < 4; q++) {
            float4 pv = *((const float4*)(g_P + didx[p] * 64 + tx * 16) + q);
            float4 qv = *((const float4*)(g_Q + sidx[p] * 64 + tx * 16) + q);
            acc[p][q * 4 + 0] = pv.x + qv.x;
            acc[p][q * 4 + 1] = pv.y + qv.y;
            acc[p][q * 4 + 2] = pv.z + qv.z;
            acc[p][q * 4 + 3] = pv.w + qv.w;
        }
    }

    // ---- stage e tile transposed: 128 edges x 16 = 512 float4 loads ----
#pragma unroll
    for (int r = 0; r < 4; r++) {
        int idx = r * 128 + tid;                     // 0..511
        float4 v = ((const float4*)e_in)[base * 4 + idx];
        int edge = idx >> 2, part = idx & 3;
        s_ET[part * 4 + 0][edge] = v.x;
        s_ET[part * 4 + 1][edge] = v.y;
        s_ET[part * 4 + 2][edge] = v.z;
        s_ET[part * 4 + 3][edge] = v.w;
    }
    // ---- stage W1c interleaved ----
#pragma unroll
    for (int r = 0; r < 8; r++) {
        int t = r * 128 + tid;                       // 0..1023
        int k = t >> 6, rem = t & 63;
        int q = rem >> 4, txx = (rem >> 2) & 3, i = rem & 3;
        s_W1x[t] = W1[(32 + k) * 64 + txx * 16 + q * 4 + i];
    }
    // ---- stage W2 interleaved ----
#pragma unroll
    for (int r = 0; r < 8; r++) {
        int t = r * 128 + tid;                       // 0..1023
        int jj = t >> 6, rem = t & 63;
        int cq = rem >> 4, txx = (rem >> 2) & 3, i = rem & 3;
        s_W2x[t] = W2[(txx * 16 + jj) * 16 + cq * 4 + i];
    }
    if (tid < 16) s_b2[tid] = b2[tid];
    __syncthreads();

    // ---- GEMM1: acc += e @ W1c.  Per k: 1 LDS.128 e (4 edges) + 4 LDS.128 w ----
#pragma unroll
    for (int k = 0; k < 16; k++) {
        float4 ev = *(const float4*)&s_ET[k][eb];
        const float av[4] = {ev.x, ev.y, ev.z, ev.w};
#pragma unroll
        for (int q = 0; q < 4; q++) {
            float4 w = *(const float4*)&s_W1x[k * 64 + q * 16 + tx * 4];
#pragma unroll
            for (int p = 0; p < 4; p++) {
                acc[p][q * 4 + 0] = fmaf(av[p], w.x, acc[p][q * 4 + 0]);
                acc[p][q * 4 + 1] = fmaf(av[p], w.y, acc[p][q * 4 + 1]);
                acc[p][q * 4 + 2] = fmaf(av[p], w.z, acc[p][q * 4 + 2]);
                acc[p][q * 4 + 3] = fmaf(av[p], w.w, acc[p][q * 4 + 3]);
            }
        }
    }

    // ---- ReLU ----
#pragma unroll
    for (int p = 0; p < 4; p++)
#pragma unroll
        for (int jj = 0; jj < 16; jj++)
            acc[p][jj] = fmaxf(acc[p][jj], 0.f);

    // ---- GEMM2 + epilogue in two 8-column halves (caps live registers) ----
#pragma unroll
    for (int h = 0; h < 2; h++) {
        float oacc[4][8];
#pragma unroll
        for (int p = 0; p < 4; p++)
#pragma unroll
            for (int c = 0; c < 8; c++) oacc[p][c] = 0.f;

#pragma unroll
        for (int jj = 0; jj < 16; jj++) {
#pragma unroll
            for (int cq2 = 0; cq2 < 2; cq2++) {
                int cq = h * 2 + cq2;
                float4 w = *(const float4*)&s_W2x[jj * 64 + cq * 16 + tx * 4];
#pragma unroll
                for (int p = 0; p < 4; p++) {
                    float hh = acc[p][jj];
                    oacc[p][cq2 * 4 + 0] = fmaf(hh, w.x, oacc[p][cq2 * 4 + 0]);
                    oacc[p][cq2 * 4 + 1] = fmaf(hh, w.y, oacc[p][cq2 * 4 + 1]);
                    oacc[p][cq2 * 4 + 2] = fmaf(hh, w.z, oacc[p][cq2 * 4 + 2]);
                    oacc[p][cq2 * 4 + 3] = fmaf(hh, w.w, oacc[p][cq2 * 4 + 3]);
                }
            }
        }
        // butterfly over the 4 tx lanes (xor 1, 2)
#pragma unroll
        for (int p = 0; p < 4; p++)
#pragma unroll
            for (int c = 0; c < 8; c++) {
                float v = oacc[p][c];
                v += __shfl_xor_sync(0xffffffffu, v, 1);
                v += __shfl_xor_sync(0xffffffffu, v, 2);
                oacc[p][c] = v;
            }
        // lane tx writes its 2 columns of this half: c = h*8 + tx*2 + {0,1}
        float bb0 = s_b2[h * 8 + tx * 2 + 0];
        float bb1 = s_b2[h * 8 + tx * 2 + 1];
#pragma unroll
        for (int p = 0; p < 4; p++) {
            float v0 = oacc[p][tx * 2 + 0] + bb0;
            float v1 = oacc[p][tx * 2 + 1] + bb1;
            int edge = base + eb + p;
            float2 ov = make_float2(v0, v1);
            *(float2*)&e_out[edge * 16 + h * 8 + tx * 2] = ov;
            float* ap = g_agg + didx[p] * 16 + h * 8 + tx * 2;
            atomicAdd(ap + 0, v0);
            atomicAdd(ap + 1, v1);
        }
    }
}

// ---------------------------------------------------------------------------
// K3: node MLP  x_new = fO(concat(x, agg)). One node per thread; weights in smem.
// ---------------------------------------------------------------------------
__global__ void __launch_bounds__(128) node_kernel(
    const float* __restrict__ x,
    const float* __restrict__ W1, const float* __restrict__ b1,
    const float* __restrict__ W2, const float* __restrict__ b2,
    float* __restrict__ x_out)
{
    __shared__ float sW1[32 * 64];
    __shared__ float sW2[64 * 16];
    __shared__ float sb1[64];
    __shared__ float sb2[16];
    int tid = threadIdx.x;
#pragma unroll
    for (int r = 0; r < 16; r++) sW1[r * 128 + tid] = W1[r * 128 + tid];
#pragma unroll
    for (int r = 0; r < 8; r++) sW2[r * 128 + tid] = W2[r * 128 + tid];
    if (tid < 64) sb1[tid] = b1[tid];
    if (tid < 16) sb2[tid] = b2[tid];
    __syncthreads();

    int n = blockIdx.x * 128 + tid;
    if (n >= NN) return;

    float in[32];
#pragma unroll
    for (int q = 0; q < 4; q++) {
        float4 v = ((const float4*)x)[n * 4 + q];
        in[q * 4 + 0] = v.x; in[q * 4 + 1] = v.y;
        in[q * 4 + 2] = v.z; in[q * 4 + 3] = v.w;
        float4 a = ((const float4*)g_agg)[n * 4 + q];
        in[16 + q * 4 + 0] = a.x; in[16 + q * 4 + 1] = a.y;
        in[16 + q * 4 + 2] = a.z; in[16 + q * 4 + 3] = a.w;
    }
    float o[16];
#pragma unroll
    for (int c = 0; c < 16; c++) o[c] = sb2[c];
    for (int j = 0; j < 64; j++) {                   // keep j-loop rolled (I-cache)
        float h = sb1[j];
#pragma unroll
        for (int k = 0; k < 32; k++) h = fmaf(in[k], sW1[k * 64 + j], h);
        h = fmaxf(h, 0.f);
#pragma unroll
        for (int c = 0; c < 16; c++) o[c] = fmaf(h, sW2[j * 16 + c], o[c]);
    }
#pragma unroll
    for (int q = 0; q < 4; q++)
        ((float4*)x_out)[n * 4 + q] =
            make_float4(o[q * 4 + 0], o[q * 4 + 1], o[q * 4 + 2], o[q * 4 + 3]);
}

// ---------------------------------------------------------------------------
extern "C" void kernel_launch(void* const* d_in, const int* in_sizes, int n_in,
                              void* d_out, int out_size)
{
    const float* x     = (const float*)d_in[0];
    const int*   ei    = (const int*)d_in[1];    // edge_index: int32 (JAX x64 disabled)
    const float* e     = (const float*)d_in[2];
    const float* fRW1  = (const float*)d_in[3];
    const float* fRb1  = (const float*)d_in[4];
    const float* fRW2  = (const float*)d_in[5];
    const float* fRb2  = (const float*)d_in[6];
    const float* fOW1  = (const float*)d_in[7];
    const float* fOb1  = (const float*)d_in[8];
    const float* fOW2  = (const float*)d_in[9];
    const float* fOb2  = (const float*)d_in[10];

    float* x_new = (float*)d_out;            // [NN, 16]
    float* e_new = x_new + NN * 16;          // [NE, 16]

    const int EB = NE / 128;                 // 12500 edge blocks total
    const int Q  = EB / 4;                   // 4 quarter launches (profiling slots)

    precompute_pq<<<(NN * 64) / 256, 256>>>(x, fRW1, fRb1);
    zero_agg_kernel<<<(NN * 16 / 4 + 255) / 256, 256>>>();
    edge_kernel<<<Q, 128>>>(ei, e, fRW1, fRW2, fRb2, e_new, 0 * Q);
    edge_kernel<<<Q, 128>>>(ei, e, fRW1, fRW2, fRb2, e_new, 1 * Q);
    edge_kernel<<<Q, 128>>>(ei, e, fRW1, fRW2, fRb2, e_new, 2 * Q);
    edge_kernel<<<Q, 128>>>(ei, e, fRW1, fRW2, fRb2, e_new, 3 * Q);
    node_kernel<<<(NN + 127) / 128, 128>>>(x, fOW1, fOb1, fOW2, fOb2, x_new);
}